// round 2
// baseline (speedup 1.0000x reference)
#include <cuda_runtime.h>
#include <math.h>

// Problem constants
#define B_  64
#define M_  16
#define A_  128
#define H_  128
#define P_  16
#define NATOM 100
#define NFP   2048
#define NTAB  (NATOM + NFP)   // 2148 combined projected rows

// Scratch (allocation-free rule: __device__ globals)
__device__ float g_proj[NTAB * H_];          // A_proj (with b_in folded) ++ F_proj
__device__ float g_mol[B_ * M_ * H_];        // per-molecule mean embeddings

// ---------------------------------------------------------------------------
// Kernel 1: projected tables.
//   rows t<100:  g_proj[t]     = atom_emb[t]   @ W_in[0:128]   + b_in
//   rows t>=100: g_proj[t]     = fp_emb[t-100] @ W_in[128:256]
// Block layout: blocks 0..6 cover atom rows (16 rows each, guard <100),
// blocks 7..134 cover the 2048 fp rows (16 each). 128 threads = output col h.
// ---------------------------------------------------------------------------
__global__ void proj_kernel(const float* __restrict__ atom_emb,
                            const float* __restrict__ fp_emb,
                            const float* __restrict__ W_in,
                            const float* __restrict__ b_in) {
    const int h = threadIdx.x;
    const bool is_atom = (blockIdx.x < 7);
    const int row0 = is_atom ? blockIdx.x * 16 : (blockIdx.x - 7) * 16;  // local row base
    const int wbase = is_atom ? 0 : (H_ * H_);   // W_in rows 128..255 for fp

    __shared__ float s_e[16][H_];
    #pragma unroll
    for (int r = 0; r < 16; r++) {
        int t = row0 + r;
        float v = 0.0f;
        if (is_atom) {
            if (t < NATOM) v = atom_emb[t * H_ + h];
        } else {
            v = fp_emb[t * H_ + h];
        }
        s_e[r][h] = v;
    }
    __syncthreads();

    float acc[16];
    #pragma unroll
    for (int r = 0; r < 16; r++) acc[r] = 0.0f;

    #pragma unroll 4
    for (int d = 0; d < H_; d++) {
        float w = W_in[wbase + d * H_ + h];   // coalesced, L1-resident across blocks
        #pragma unroll
        for (int r = 0; r < 16; r++) acc[r] += s_e[r][d] * w;  // smem broadcast
    }

    float bias = is_atom ? b_in[h] : 0.0f;
    #pragma unroll
    for (int r = 0; r < 16; r++) {
        int t = row0 + r;
        if (is_atom) {
            if (t < NATOM) g_proj[t * H_ + h] = acc[r] + bias;
        } else {
            g_proj[(NATOM + t) * H_ + h] = acc[r];
        }
    }
}

// ---------------------------------------------------------------------------
// Kernel 2: per-molecule mean of relu(A_proj[af] + F_proj[fp]).
// One block per (b,m) molecule; 128 threads = embedding dim h.
// L2-bandwidth-bound: 1024 blocks x 128 atoms x 2 x 512B gathered rows.
// ---------------------------------------------------------------------------
__global__ void mol_kernel(const int* __restrict__ atom_features,
                           const int* __restrict__ fingerprints) {
    const int bm = blockIdx.x;        // 0..1023
    const int h = threadIdx.x;        // 0..127

    __shared__ int s_a[A_];
    __shared__ int s_f[A_];
    s_a[h] = atom_features[bm * A_ + h] * H_;            // row byte-offsets in elements
    s_f[h] = (NATOM + fingerprints[bm * A_ + h]) * H_;
    __syncthreads();

    float acc0 = 0.0f, acc1 = 0.0f, acc2 = 0.0f, acc3 = 0.0f;
    #pragma unroll 4
    for (int a = 0; a < A_; a += 4) {
        float pa0 = g_proj[s_a[a + 0] + h];
        float pf0 = g_proj[s_f[a + 0] + h];
        float pa1 = g_proj[s_a[a + 1] + h];
        float pf1 = g_proj[s_f[a + 1] + h];
        float pa2 = g_proj[s_a[a + 2] + h];
        float pf2 = g_proj[s_f[a + 2] + h];
        float pa3 = g_proj[s_a[a + 3] + h];
        float pf3 = g_proj[s_f[a + 3] + h];
        acc0 += fmaxf(pa0 + pf0, 0.0f);
        acc1 += fmaxf(pa1 + pf1, 0.0f);
        acc2 += fmaxf(pa2 + pf2, 0.0f);
        acc3 += fmaxf(pa3 + pf3, 0.0f);
    }
    g_mol[bm * H_ + h] = (acc0 + acc1 + acc2 + acc3) * (1.0f / (float)A_);
}

// ---------------------------------------------------------------------------
// Kernel 3: mixing weights + phys mix + LayerNorm + 2-layer MLP head.
// One block per batch item b; 128 threads.
// ---------------------------------------------------------------------------
__global__ void head_kernel(const float* __restrict__ phys,
                            const float* __restrict__ ratios,
                            const float* __restrict__ ln_g,
                            const float* __restrict__ ln_b,
                            const float* __restrict__ W1,
                            const float* __restrict__ b1,
                            const float* __restrict__ W2,
                            const float* __restrict__ b2,
                            float* __restrict__ out) {
    const int b = blockIdx.x;
    const int h = threadIdx.x;

    __shared__ float s_w[M_];
    __shared__ float s_z[H_ + P_];
    __shared__ float s_zn[H_ + P_];
    __shared__ float s_red[8];

    if (h < M_) s_w[h] = ratios[b * M_ + h];
    __syncthreads();
    if (h == 0) {
        float s = 0.0f;
        #pragma unroll
        for (int m = 0; m < M_; m++) s += s_w[m];
        float inv = 1.0f / (s + 1e-8f);
        #pragma unroll
        for (int m = 0; m < M_; m++) s_w[m] *= inv;
    }
    __syncthreads();

    // mix_h[b][h]
    float acc = 0.0f;
    #pragma unroll
    for (int m = 0; m < M_; m++) acc += s_w[m] * g_mol[(b * M_ + m) * H_ + h];
    s_z[h] = acc;

    // mix_p[b][h] for h<16 (with nan_to_num on phys)
    if (h < P_) {
        float accp = 0.0f;
        #pragma unroll
        for (int m = 0; m < M_; m++) {
            float v = phys[(b * M_ + m) * P_ + h];
            if (v != v) v = 0.0f;                       // nan -> 0
            else if (isinf(v)) v = (v > 0.0f) ? 1000.0f : -1000.0f;
            accp += s_w[m] * v;
        }
        s_z[H_ + h] = accp;
    }
    __syncthreads();

    // LayerNorm over 144 elements: mean / var via block reduction
    float x  = s_z[h];
    float x2 = x * x;
    if (h < P_) { float e = s_z[H_ + h]; x += e; x2 += e * e; }
    #pragma unroll
    for (int o = 16; o > 0; o >>= 1) {
        x  += __shfl_xor_sync(0xFFFFFFFFu, x,  o);
        x2 += __shfl_xor_sync(0xFFFFFFFFu, x2, o);
    }
    int warp = h >> 5;
    if ((h & 31) == 0) { s_red[warp] = x; s_red[4 + warp] = x2; }
    __syncthreads();
    float sum  = s_red[0] + s_red[1] + s_red[2] + s_red[3];
    float sum2 = s_red[4] + s_red[5] + s_red[6] + s_red[7];
    const float N = (float)(H_ + P_);
    float mu  = sum / N;
    float var = sum2 / N - mu * mu;
    float rstd = rsqrtf(var + 1e-5f);

    s_zn[h] = (s_z[h] - mu) * rstd * ln_g[h] + ln_b[h];
    if (h < P_) s_zn[H_ + h] = (s_z[H_ + h] - mu) * rstd * ln_g[H_ + h] + ln_b[H_ + h];
    __syncthreads();

    // MLP head: relu(zn @ W1 + b1) @ W2 + b2
    float t = b1[h];
    #pragma unroll 4
    for (int d = 0; d < H_ + P_; d++) t += s_zn[d] * W1[d * H_ + h];
    float r = fmaxf(t, 0.0f) * W2[h];

    #pragma unroll
    for (int o = 16; o > 0; o >>= 1) r += __shfl_xor_sync(0xFFFFFFFFu, r, o);
    if ((h & 31) == 0) s_red[warp] = r;
    __syncthreads();
    if (h == 0) {
        float y = s_red[0] + s_red[1] + s_red[2] + s_red[3] + b2[0];
        if (y != y) y = 0.0f;
        else if (isinf(y)) y = (y > 0.0f) ? 3.4028234663852886e38f : -3.4028234663852886e38f;
        out[b] = y;
    }
}

extern "C" void kernel_launch(void* const* d_in, const int* in_sizes, int n_in,
                              void* d_out, int out_size) {
    const int*   atom_features = (const int*)  d_in[0];
    const int*   fingerprints  = (const int*)  d_in[1];
    const float* phys          = (const float*)d_in[2];
    const float* ratios        = (const float*)d_in[3];
    const float* atom_emb      = (const float*)d_in[4];
    const float* fp_emb        = (const float*)d_in[5];
    const float* W_in          = (const float*)d_in[6];
    const float* b_in          = (const float*)d_in[7];
    const float* ln_g          = (const float*)d_in[8];
    const float* ln_b          = (const float*)d_in[9];
    const float* W1            = (const float*)d_in[10];
    const float* b1            = (const float*)d_in[11];
    const float* W2            = (const float*)d_in[12];
    const float* b2            = (const float*)d_in[13];
    float* out = (float*)d_out;

    // 7 atom blocks (100 rows) + 128 fp blocks (2048 rows)
    proj_kernel<<<135, 128>>>(atom_emb, fp_emb, W_in, b_in);
    mol_kernel<<<B_ * M_, 128>>>(atom_features, fingerprints);
    head_kernel<<<B_, 128>>>(phys, ratios, ln_g, ln_b, W1, b1, W2, b2, out);
}

// round 3
// speedup vs baseline: 1.4319x; 1.4319x over previous
#include <cuda_runtime.h>
#include <math.h>

// Problem constants
#define B_  64
#define M_  16
#define A_  128
#define H_  128
#define P_  16
#define NATOM 100
#define NFP   2048
#define NTAB  (NATOM + NFP)   // 2148 combined projected rows

// Scratch (allocation-free rule: __device__ globals)
__device__ float g_proj[NTAB * H_];          // A_proj (with b_in folded) ++ F_proj
__device__ float g_mol[B_ * M_ * H_];        // per-molecule mean embeddings

// ---------------------------------------------------------------------------
// Kernel 1: projected tables (v2: 512 threads, K-split x4, transposed E tile).
//   rows t<100:  g_proj[t] = atom_emb[t]   @ W_in[0:128]   + b_in
//   rows t>=100: g_proj[t] = fp_emb[t-100] @ W_in[128:256]
// Blocks 0..6 cover the 100 atom rows (16 each, guarded); blocks 7..134 cover
// the 2048 fp rows (16 each). tid = kslice(4) x h(128). Each kslice
// accumulates 32 K-steps; partials reduced through smem.
// ---------------------------------------------------------------------------
__global__ __launch_bounds__(512, 1)
void proj_kernel(const float* __restrict__ atom_emb,
                 const float* __restrict__ fp_emb,
                 const float* __restrict__ W_in,
                 const float* __restrict__ b_in) {
    const int tid = threadIdx.x;
    const int h  = tid & 127;
    const int ks = tid >> 7;            // 0..3
    const bool is_atom = (blockIdx.x < 7);
    const int row0  = is_atom ? blockIdx.x * 16 : (blockIdx.x - 7) * 16;
    const int wbase = is_atom ? 0 : (H_ * H_);

    __shared__ __align__(16) float s_eT[H_][16];   // [d][r] transposed tile (8 KB)
    __shared__ float s_p[4][16 * H_];              // K-slice partials (32 KB)

    // Load E tile transposed: 2048 elements / 512 threads = 4 each.
    #pragma unroll
    for (int i = tid; i < 16 * H_; i += 512) {
        int r = i >> 7, d = i & 127;
        int t = row0 + r;
        float v = 0.0f;
        if (is_atom) { if (t < NATOM) v = atom_emb[t * H_ + d]; }
        else         { v = fp_emb[t * H_ + d]; }
        s_eT[d][r] = v;
    }
    __syncthreads();

    float acc[16];
    #pragma unroll
    for (int r = 0; r < 16; r++) acc[r] = 0.0f;

    const float* __restrict__ Wp = W_in + wbase + h;
    const int d0 = ks * 32;
    #pragma unroll 8
    for (int dd = 0; dd < 32; dd++) {
        const int d = d0 + dd;
        const float w = Wp[d * H_];                       // coalesced LDG
        const float4 e0 = *(const float4*)&s_eT[d][0];    // 4x LDS.128 broadcast
        const float4 e1 = *(const float4*)&s_eT[d][4];
        const float4 e2 = *(const float4*)&s_eT[d][8];
        const float4 e3 = *(const float4*)&s_eT[d][12];
        acc[0]  += e0.x * w; acc[1]  += e0.y * w; acc[2]  += e0.z * w; acc[3]  += e0.w * w;
        acc[4]  += e1.x * w; acc[5]  += e1.y * w; acc[6]  += e1.z * w; acc[7]  += e1.w * w;
        acc[8]  += e2.x * w; acc[9]  += e2.y * w; acc[10] += e2.z * w; acc[11] += e2.w * w;
        acc[12] += e3.x * w; acc[13] += e3.y * w; acc[14] += e3.z * w; acc[15] += e3.w * w;
    }

    #pragma unroll
    for (int r = 0; r < 16; r++) s_p[ks][r * H_ + h] = acc[r];
    __syncthreads();

    // Reduce 4 partials + store: 2048 outputs / 512 threads = 4 each.
    #pragma unroll
    for (int i = tid; i < 16 * H_; i += 512) {
        int r = i >> 7, hc = i & 127;
        int t = row0 + r;
        float v = s_p[0][i] + s_p[1][i] + s_p[2][i] + s_p[3][i];
        if (is_atom) { if (t < NATOM) g_proj[t * H_ + hc] = v + b_in[hc]; }
        else         { g_proj[(NATOM + t) * H_ + hc] = v; }
    }
}

// ---------------------------------------------------------------------------
// Kernel 2: per-molecule mean of relu(A_proj[af] + F_proj[fp]).
// One block per (b,m) molecule; 128 threads = embedding dim h.
// ---------------------------------------------------------------------------
__global__ void mol_kernel(const int* __restrict__ atom_features,
                           const int* __restrict__ fingerprints) {
    const int bm = blockIdx.x;        // 0..1023
    const int h = threadIdx.x;        // 0..127

    __shared__ int s_a[A_];
    __shared__ int s_f[A_];
    s_a[h] = atom_features[bm * A_ + h] * H_;            // row offsets in elements
    s_f[h] = (NATOM + fingerprints[bm * A_ + h]) * H_;
    __syncthreads();

    float acc0 = 0.0f, acc1 = 0.0f, acc2 = 0.0f, acc3 = 0.0f;
    #pragma unroll 4
    for (int a = 0; a < A_; a += 4) {
        float pa0 = g_proj[s_a[a + 0] + h];
        float pf0 = g_proj[s_f[a + 0] + h];
        float pa1 = g_proj[s_a[a + 1] + h];
        float pf1 = g_proj[s_f[a + 1] + h];
        float pa2 = g_proj[s_a[a + 2] + h];
        float pf2 = g_proj[s_f[a + 2] + h];
        float pa3 = g_proj[s_a[a + 3] + h];
        float pf3 = g_proj[s_f[a + 3] + h];
        acc0 += fmaxf(pa0 + pf0, 0.0f);
        acc1 += fmaxf(pa1 + pf1, 0.0f);
        acc2 += fmaxf(pa2 + pf2, 0.0f);
        acc3 += fmaxf(pa3 + pf3, 0.0f);
    }
    g_mol[bm * H_ + h] = (acc0 + acc1 + acc2 + acc3) * (1.0f / (float)A_);
}

// ---------------------------------------------------------------------------
// Kernel 3: mixing weights + phys mix + LayerNorm + 2-layer MLP head.
// One block per batch item b; 128 threads.
// ---------------------------------------------------------------------------
__global__ void head_kernel(const float* __restrict__ phys,
                            const float* __restrict__ ratios,
                            const float* __restrict__ ln_g,
                            const float* __restrict__ ln_b,
                            const float* __restrict__ W1,
                            const float* __restrict__ b1,
                            const float* __restrict__ W2,
                            const float* __restrict__ b2,
                            float* __restrict__ out) {
    const int b = blockIdx.x;
    const int h = threadIdx.x;

    __shared__ float s_w[M_];
    __shared__ float s_z[H_ + P_];
    __shared__ float s_zn[H_ + P_];
    __shared__ float s_red[8];

    if (h < M_) s_w[h] = ratios[b * M_ + h];
    __syncthreads();
    if (h == 0) {
        float s = 0.0f;
        #pragma unroll
        for (int m = 0; m < M_; m++) s += s_w[m];
        float inv = 1.0f / (s + 1e-8f);
        #pragma unroll
        for (int m = 0; m < M_; m++) s_w[m] *= inv;
    }
    __syncthreads();

    // mix_h[b][h]
    float acc = 0.0f;
    #pragma unroll
    for (int m = 0; m < M_; m++) acc += s_w[m] * g_mol[(b * M_ + m) * H_ + h];
    s_z[h] = acc;

    // mix_p[b][h] for h<16 (with nan_to_num on phys)
    if (h < P_) {
        float accp = 0.0f;
        #pragma unroll
        for (int m = 0; m < M_; m++) {
            float v = phys[(b * M_ + m) * P_ + h];
            if (v != v) v = 0.0f;                       // nan -> 0
            else if (isinf(v)) v = (v > 0.0f) ? 1000.0f : -1000.0f;
            accp += s_w[m] * v;
        }
        s_z[H_ + h] = accp;
    }
    __syncthreads();

    // LayerNorm over 144 elements
    float x  = s_z[h];
    float x2 = x * x;
    if (h < P_) { float e = s_z[H_ + h]; x += e; x2 += e * e; }
    #pragma unroll
    for (int o = 16; o > 0; o >>= 1) {
        x  += __shfl_xor_sync(0xFFFFFFFFu, x,  o);
        x2 += __shfl_xor_sync(0xFFFFFFFFu, x2, o);
    }
    int warp = h >> 5;
    if ((h & 31) == 0) { s_red[warp] = x; s_red[4 + warp] = x2; }
    __syncthreads();
    float sum  = s_red[0] + s_red[1] + s_red[2] + s_red[3];
    float sum2 = s_red[4] + s_red[5] + s_red[6] + s_red[7];
    const float N = (float)(H_ + P_);
    float mu  = sum / N;
    float var = sum2 / N - mu * mu;
    float rstd = rsqrtf(var + 1e-5f);

    s_zn[h] = (s_z[h] - mu) * rstd * ln_g[h] + ln_b[h];
    if (h < P_) s_zn[H_ + h] = (s_z[H_ + h] - mu) * rstd * ln_g[H_ + h] + ln_b[H_ + h];
    __syncthreads();

    // MLP head: relu(zn @ W1 + b1) @ W2 + b2
    float t = b1[h];
    #pragma unroll 4
    for (int d = 0; d < H_ + P_; d++) t += s_zn[d] * W1[d * H_ + h];
    float r = fmaxf(t, 0.0f) * W2[h];

    #pragma unroll
    for (int o = 16; o > 0; o >>= 1) r += __shfl_xor_sync(0xFFFFFFFFu, r, o);
    if ((h & 31) == 0) s_red[warp] = r;
    __syncthreads();
    if (h == 0) {
        float y = s_red[0] + s_red[1] + s_red[2] + s_red[3] + b2[0];
        if (y != y) y = 0.0f;
        else if (isinf(y)) y = (y > 0.0f) ? 3.4028234663852886e38f : -3.4028234663852886e38f;
        out[b] = y;
    }
}

extern "C" void kernel_launch(void* const* d_in, const int* in_sizes, int n_in,
                              void* d_out, int out_size) {
    const int*   atom_features = (const int*)  d_in[0];
    const int*   fingerprints  = (const int*)  d_in[1];
    const float* phys          = (const float*)d_in[2];
    const float* ratios        = (const float*)d_in[3];
    const float* atom_emb      = (const float*)d_in[4];
    const float* fp_emb        = (const float*)d_in[5];
    const float* W_in          = (const float*)d_in[6];
    const float* b_in          = (const float*)d_in[7];
    const float* ln_g          = (const float*)d_in[8];
    const float* ln_b          = (const float*)d_in[9];
    const float* W1            = (const float*)d_in[10];
    const float* b1            = (const float*)d_in[11];
    const float* W2            = (const float*)d_in[12];
    const float* b2            = (const float*)d_in[13];
    float* out = (float*)d_out;

    proj_kernel<<<135, 512>>>(atom_emb, fp_emb, W_in, b_in);
    mol_kernel<<<B_ * M_, 128>>>(atom_features, fingerprints);
    head_kernel<<<B_, 128>>>(phys, ratios, ln_g, ln_b, W1, b1, W2, b2, out);
}